// round 5
// baseline (speedup 1.0000x reference)
#include <cuda_runtime.h>
#include <math.h>

#define B_   4
#define H_   8
#define S_   2048
#define D_   16
#define TILE 128
#define QPB  128

// ---- packed f32x2 helpers (sm_100+ PTX; gives FFMA2 in SASS) ----
__device__ __forceinline__ unsigned long long ffma2(unsigned long long a,
                                                    unsigned long long b,
                                                    unsigned long long c) {
    unsigned long long d;
    asm("fma.rn.f32x2 %0, %1, %2, %3;" : "=l"(d) : "l"(a), "l"(b), "l"(c));
    return d;
}
__device__ __forceinline__ unsigned long long fadd2(unsigned long long a,
                                                    unsigned long long b) {
    unsigned long long d;
    asm("add.rn.f32x2 %0, %1, %2;" : "=l"(d) : "l"(a), "l"(b));
    return d;
}
__device__ __forceinline__ float ex2f(float x) {
    float y; asm("ex2.approx.ftz.f32 %0, %1;" : "=f"(y) : "f"(x)); return y;
}
__device__ __forceinline__ float rcpf(float x) {
    float y; asm("rcp.approx.ftz.f32 %0, %1;" : "=f"(y) : "f"(x)); return y;
}

// p = exp(10*tanh(x)) where s = x*2*log2(e) is computed by the dot product:
//   e2x = 2^s = exp(2x); r = 1/(e2x+1); tanh = 1-2r; p = 2^(fma(r,-20*log2e, 10*log2e))
#define C_A  (-28.853900817779268f)  // -20*log2(e)
#define C_B  ( 14.426950408889634f)  //  10*log2(e)

__global__ __launch_bounds__(QPB)
void attn_kernel(const float* __restrict__ Q, const float* __restrict__ K,
                 const float* __restrict__ V, const int* __restrict__ mask,
                 float* __restrict__ O, float q_prescale /* SCALE*2*log2(e) */) {
    __shared__ float Ks[TILE * D_];
    __shared__ float Vs[TILE * D_];
    __shared__ int   s_wcnt[4];     // per-warp kept-key counts

    const int bh   = blockIdx.y;               // 0..31
    const int b    = bh / H_;
    const int q    = blockIdx.x * QPB + threadIdx.x;
    const int wid  = threadIdx.x >> 5;
    const int lane = threadIdx.x & 31;
    const long long base = (long long)bh * S_ * D_;

    // Load and prescale this thread's query row, pack to f32x2
    unsigned long long qp[8];
    {
        const float4* qg = (const float4*)(Q + base + (long long)q * D_);
        float qr[D_];
        #pragma unroll
        for (int i = 0; i < 4; i++) {
            float4 v = qg[i];
            qr[4*i+0] = v.x; qr[4*i+1] = v.y; qr[4*i+2] = v.z; qr[4*i+3] = v.w;
        }
        #pragma unroll
        for (int i = 0; i < 8; i++) {
            float a = qr[2*i] * q_prescale, c = qr[2*i+1] * q_prescale;
            asm("mov.b64 %0, {%1, %2};" : "=l"(qp[i]) : "f"(a), "f"(c));
        }
    }

    unsigned long long accp[8];
    #pragma unroll
    for (int i = 0; i < 8; i++) accp[i] = 0ull;   // packed (0.f, 0.f)
    float lsum = 0.f;

    // mask is 4-byte (bool upcast to int32 or float32); bitwise !=0 handles both
    const int* mrow = mask + (long long)b * S_;

    for (int t0 = 0; t0 < S_; t0 += TILE) {
        // ---- deterministic ballot-based compaction (no atomics) ----
        const int j    = t0 + threadIdx.x;
        const int keep = (mrow[j] == 0);
        const unsigned bal = __ballot_sync(0xFFFFFFFFu, keep);
        if (lane == 0) s_wcnt[wid] = __popc(bal);
        __syncthreads();   // publishes counts; also guards prev-tile readers vs new writes
        int wbase = 0, total = 0;
        #pragma unroll
        for (int w = 0; w < 4; w++) {
            int c = s_wcnt[w];
            if (w < wid) wbase += c;
            total += c;
        }
        if (keep) {
            const int pos = wbase + __popc(bal & ((1u << lane) - 1u));
            const float4* kg = (const float4*)(K + base + (long long)j * D_);
            const float4* vg = (const float4*)(V + base + (long long)j * D_);
            float4* kd = (float4*)(Ks + pos * D_);
            float4* vd = (float4*)(Vs + pos * D_);
            #pragma unroll
            for (int i = 0; i < 4; i++) { kd[i] = kg[i]; vd[i] = vg[i]; }
        }
        __syncthreads();
        const int cnt = total;

        #pragma unroll 2
        for (int jj = 0; jj < cnt; ++jj) {
            // dot(q,k)*SCALE*2*log2e — two parallel packed-FMA chains
            const ulonglong2* kr = (const ulonglong2*)(Ks + jj * D_);
            ulonglong2 k01 = kr[0], k23 = kr[1], k45 = kr[2], k67 = kr[3];
            unsigned long long d0, d1;
            d0 = ffma2(qp[0], k01.x, 0ull);
            d1 = ffma2(qp[1], k01.y, 0ull);
            d0 = ffma2(qp[2], k23.x, d0);
            d1 = ffma2(qp[3], k23.y, d1);
            d0 = ffma2(qp[4], k45.x, d0);
            d1 = ffma2(qp[5], k45.y, d1);
            d0 = ffma2(qp[6], k67.x, d0);
            d1 = ffma2(qp[7], k67.y, d1);
            unsigned long long ds = fadd2(d0, d1);
            float lo, hi;
            asm("mov.b64 {%0, %1}, %2;" : "=f"(lo), "=f"(hi) : "l"(ds));
            const float s = lo + hi;                 // = 2*log2e*SCALE*(q.k)

            // p = exp(10*tanh(SCALE*(q.k)))   (logit in [-10,10] => no running max needed)
            const float e  = ex2f(s);
            const float r  = rcpf(e + 1.f);
            const float p  = ex2f(fmaf(r, C_A, C_B));
            lsum += p;

            unsigned long long pp;
            asm("mov.b64 %0, {%1, %1};" : "=l"(pp) : "f"(p));
            const ulonglong2* vr = (const ulonglong2*)(Vs + jj * D_);
            ulonglong2 v01 = vr[0], v23 = vr[1], v45 = vr[2], v67 = vr[3];
            accp[0] = ffma2(pp, v01.x, accp[0]);
            accp[1] = ffma2(pp, v01.y, accp[1]);
            accp[2] = ffma2(pp, v23.x, accp[2]);
            accp[3] = ffma2(pp, v23.y, accp[3]);
            accp[4] = ffma2(pp, v45.x, accp[4]);
            accp[5] = ffma2(pp, v45.y, accp[5]);
            accp[6] = ffma2(pp, v67.x, accp[6]);
            accp[7] = ffma2(pp, v67.y, accp[7]);
        }
        __syncthreads();
    }

    // Epilogue: normalize and store
    const float inv = 1.0f / lsum;
    float4* og = (float4*)(O + base + (long long)q * D_);
    #pragma unroll
    for (int i = 0; i < 4; i++) {
        float x0, x1, y0, y1;
        asm("mov.b64 {%0, %1}, %2;" : "=f"(x0), "=f"(x1) : "l"(accp[2*i]));
        asm("mov.b64 {%0, %1}, %2;" : "=f"(y0), "=f"(y1) : "l"(accp[2*i+1]));
        float4 o; o.x = x0 * inv; o.y = x1 * inv; o.z = y0 * inv; o.w = y1 * inv;
        og[i] = o;
    }
}

extern "C" void kernel_launch(void* const* d_in, const int* in_sizes, int n_in,
                              void* d_out, int out_size) {
    const float* Q = (const float*)d_in[0];
    const float* K = (const float*)d_in[1];
    const float* V = (const float*)d_in[2];
    const int*   mask = (const int*)d_in[3];
    float* O = (float*)d_out;

    // SCALE = log(400)/log(50)/sqrt(16); fold in 2*log2(e) for the tanh exp
    const float q_prescale =
        (float)((log(400.0) / log(50.0) / 4.0) * 2.0 * 1.4426950408889634);

    dim3 grid(S_ / QPB, B_ * H_);
    attn_kernel<<<grid, QPB>>>(Q, K, V, mask, O, q_prescale);
}

// round 6
// speedup vs baseline: 1.2428x; 1.2428x over previous
#include <cuda_runtime.h>
#include <math.h>

#define B_   4
#define H_   8
#define S_   2048
#define D_   16
#define TILE 128
#define QPB  128          // threads per CTA
#define QPT  2            // queries per thread
#define QTILE (QPB*QPT)   // 256 queries per CTA

// ---- packed f32x2 helpers (sm_100+ PTX; FFMA2 in SASS) ----
__device__ __forceinline__ unsigned long long ffma2(unsigned long long a,
                                                    unsigned long long b,
                                                    unsigned long long c) {
    unsigned long long d;
    asm("fma.rn.f32x2 %0, %1, %2, %3;" : "=l"(d) : "l"(a), "l"(b), "l"(c));
    return d;
}
__device__ __forceinline__ unsigned long long fadd2(unsigned long long a,
                                                    unsigned long long b) {
    unsigned long long d;
    asm("add.rn.f32x2 %0, %1, %2;" : "=l"(d) : "l"(a), "l"(b));
    return d;
}
__device__ __forceinline__ float ex2f(float x) {
    float y; asm("ex2.approx.ftz.f32 %0, %1;" : "=f"(y) : "f"(x)); return y;
}
__device__ __forceinline__ float rcpf(float x) {
    float y; asm("rcp.approx.ftz.f32 %0, %1;" : "=f"(y) : "f"(x)); return y;
}

// p = exp(10*tanh(x)); s = 2x*log2e comes out of the prescaled dot product:
// e = 2^s = exp(2x); r = 1/(e+1); p = 2^(fma(r, -20*log2e, 10*log2e))
#define C_A  (-28.853900817779268f)  // -20*log2(e)
#define C_B  ( 14.426950408889634f)  //  10*log2(e)

struct KRow { ulonglong2 r0, r1, r2, r3; };   // 16 floats packed as f32x2

__device__ __forceinline__ float dot16(const unsigned long long* qp, const KRow& k) {
    unsigned long long d0, d1;
    d0 = ffma2(qp[0], k.r0.x, 0ull);
    d1 = ffma2(qp[1], k.r0.y, 0ull);
    d0 = ffma2(qp[2], k.r1.x, d0);
    d1 = ffma2(qp[3], k.r1.y, d1);
    d0 = ffma2(qp[4], k.r2.x, d0);
    d1 = ffma2(qp[5], k.r2.y, d1);
    d0 = ffma2(qp[6], k.r3.x, d0);
    d1 = ffma2(qp[7], k.r3.y, d1);
    unsigned long long ds = fadd2(d0, d1);
    float lo, hi;
    asm("mov.b64 {%0, %1}, %2;" : "=f"(lo), "=f"(hi) : "l"(ds));
    return lo + hi;
}
__device__ __forceinline__ float pfun(float s) {
    const float e = ex2f(s);
    const float r = rcpf(e + 1.f);
    return ex2f(fmaf(r, C_A, C_B));
}
__device__ __forceinline__ void pv_acc(unsigned long long* acc, float p, const KRow& v) {
    unsigned long long pp;
    asm("mov.b64 %0, {%1, %1};" : "=l"(pp) : "f"(p));
    acc[0] = ffma2(pp, v.r0.x, acc[0]);
    acc[1] = ffma2(pp, v.r0.y, acc[1]);
    acc[2] = ffma2(pp, v.r1.x, acc[2]);
    acc[3] = ffma2(pp, v.r1.y, acc[3]);
    acc[4] = ffma2(pp, v.r2.x, acc[4]);
    acc[5] = ffma2(pp, v.r2.y, acc[5]);
    acc[6] = ffma2(pp, v.r3.x, acc[6]);
    acc[7] = ffma2(pp, v.r3.y, acc[7]);
}

__global__ __launch_bounds__(QPB, 2)
void attn_kernel(const float* __restrict__ Q, const float* __restrict__ K,
                 const float* __restrict__ V, const int* __restrict__ mask,
                 float* __restrict__ O, float q_prescale /* SCALE*2*log2(e) */) {
    __shared__ float Ks[TILE * D_];
    __shared__ float Vs[TILE * D_];
    __shared__ int   s_wcnt[4];

    const int bh   = blockIdx.y;
    const int b    = bh / H_;
    const int tid  = threadIdx.x;
    const int wid  = tid >> 5;
    const int lane = tid & 31;
    const int q0   = blockIdx.x * QTILE + tid;      // second query: q0 + QPB
    const long long base = (long long)bh * S_ * D_;

    // Load + prescale both query rows, packed f32x2
    unsigned long long qp0[8], qp1[8];
    {
        const float4* qg0 = (const float4*)(Q + base + (long long)q0 * D_);
        const float4* qg1 = (const float4*)(Q + base + (long long)(q0 + QPB) * D_);
        float a[D_], c[D_];
        #pragma unroll
        for (int i = 0; i < 4; i++) {
            float4 u = qg0[i], v = qg1[i];
            a[4*i+0]=u.x; a[4*i+1]=u.y; a[4*i+2]=u.z; a[4*i+3]=u.w;
            c[4*i+0]=v.x; c[4*i+1]=v.y; c[4*i+2]=v.z; c[4*i+3]=v.w;
        }
        #pragma unroll
        for (int i = 0; i < 8; i++) {
            float x0 = a[2*i]*q_prescale, x1 = a[2*i+1]*q_prescale;
            float y0 = c[2*i]*q_prescale, y1 = c[2*i+1]*q_prescale;
            asm("mov.b64 %0, {%1, %2};" : "=l"(qp0[i]) : "f"(x0), "f"(x1));
            asm("mov.b64 %0, {%1, %2};" : "=l"(qp1[i]) : "f"(y0), "f"(y1));
        }
    }

    unsigned long long acc0[8], acc1[8];
    #pragma unroll
    for (int i = 0; i < 8; i++) { acc0[i] = 0ull; acc1[i] = 0ull; }
    float lsum0 = 0.f, lsum1 = 0.f;

    const int* mrow = mask + (long long)b * S_;     // bool upcast to 4B; !=0 test
    int mval = mrow[tid];                           // prefetched mask for tile 0

    for (int t0 = 0; t0 < S_; t0 += TILE) {
        // ---- deterministic ballot compaction ----
        const int j    = t0 + tid;
        const int keep = (mval == 0);
        const unsigned bal = __ballot_sync(0xFFFFFFFFu, keep);
        if (lane == 0) s_wcnt[wid] = __popc(bal);

        // Issue predicated K/V global loads early (overlap with barrier)
        float4 kr[4], vr[4];
        if (keep) {
            const float4* kg = (const float4*)(K + base + (long long)j * D_);
            const float4* vg = (const float4*)(V + base + (long long)j * D_);
            #pragma unroll
            for (int i = 0; i < 4; i++) { kr[i] = kg[i]; vr[i] = vg[i]; }
        }
        // Prefetch next tile's mask
        if (t0 + TILE < S_) mval = mrow[t0 + TILE + tid];

        __syncthreads();   // publish counts; also guards prev-tile readers vs new writes
        int wbase = 0, total = 0;
        #pragma unroll
        for (int w = 0; w < 4; w++) {
            int cw = s_wcnt[w];
            if (w < wid) wbase += cw;
            total += cw;
        }
        if (keep) {
            const int pos = wbase + __popc(bal & ((1u << lane) - 1u));
            float4* kd = (float4*)(Ks + pos * D_);
            float4* vd = (float4*)(Vs + pos * D_);
            #pragma unroll
            for (int i = 0; i < 4; i++) { kd[i] = kr[i]; vd[i] = vr[i]; }
        }
        __syncthreads();
        const int cnt = total;

        const KRow* ksr = (const KRow*)Ks;
        const KRow* vsr = (const KRow*)Vs;

        int jj = 0;
        for (; jj + 2 <= cnt; jj += 2) {
            KRow kA = ksr[jj], kB = ksr[jj+1];
            // 4 independent dot chains
            float sA0 = dot16(qp0, kA);
            float sA1 = dot16(qp1, kA);
            float sB0 = dot16(qp0, kB);
            float sB1 = dot16(qp1, kB);
            // 4 independent MUFU chains
            float pA0 = pfun(sA0);
            float pA1 = pfun(sA1);
            float pB0 = pfun(sB0);
            float pB1 = pfun(sB1);
            lsum0 += pA0; lsum1 += pA1;
            lsum0 += pB0; lsum1 += pB1;
            KRow vA = vsr[jj], vB = vsr[jj+1];
            pv_acc(acc0, pA0, vA);
            pv_acc(acc1, pA1, vA);
            pv_acc(acc0, pB0, vB);
            pv_acc(acc1, pB1, vB);
        }
        if (jj < cnt) {
            KRow kA = ksr[jj];
            float sA0 = dot16(qp0, kA);
            float sA1 = dot16(qp1, kA);
            float pA0 = pfun(sA0);
            float pA1 = pfun(sA1);
            lsum0 += pA0; lsum1 += pA1;
            KRow vA = vsr[jj];
            pv_acc(acc0, pA0, vA);
            pv_acc(acc1, pA1, vA);
        }
        __syncthreads();
    }

    // Epilogue: normalize and store both query rows
    const float inv0 = 1.0f / lsum0;
    const float inv1 = 1.0f / lsum1;
    float4* og0 = (float4*)(O + base + (long long)q0 * D_);
    float4* og1 = (float4*)(O + base + (long long)(q0 + QPB) * D_);
    #pragma unroll
    for (int i = 0; i < 4; i++) {
        float x0, x1, y0, y1;
        asm("mov.b64 {%0, %1}, %2;" : "=f"(x0), "=f"(x1) : "l"(acc0[2*i]));
        asm("mov.b64 {%0, %1}, %2;" : "=f"(y0), "=f"(y1) : "l"(acc0[2*i+1]));
        float4 o; o.x = x0*inv0; o.y = x1*inv0; o.z = y0*inv0; o.w = y1*inv0;
        og0[i] = o;
        asm("mov.b64 {%0, %1}, %2;" : "=f"(x0), "=f"(x1) : "l"(acc1[2*i]));
        asm("mov.b64 {%0, %1}, %2;" : "=f"(y0), "=f"(y1) : "l"(acc1[2*i+1]));
        float4 p; p.x = x0*inv1; p.y = x1*inv1; p.z = y0*inv1; p.w = y1*inv1;
        og1[i] = p;
    }
}

extern "C" void kernel_launch(void* const* d_in, const int* in_sizes, int n_in,
                              void* d_out, int out_size) {
    const float* Q = (const float*)d_in[0];
    const float* K = (const float*)d_in[1];
    const float* V = (const float*)d_in[2];
    const int*   mask = (const int*)d_in[3];
    float* O = (float*)d_out;

    // SCALE = log(400)/log(50)/sqrt(16); fold in 2*log2(e) for the tanh exp
    const float q_prescale =
        (float)((log(400.0) / log(50.0) / 4.0) * 2.0 * 1.4426950408889634);

    dim3 grid(S_ / QTILE, B_ * H_);
    attn_kernel<<<grid, QPB>>>(Q, K, V, mask, O, q_prescale);
}